// round 5
// baseline (speedup 1.0000x reference)
#include <cuda_runtime.h>
#include <cuda_fp16.h>

#define BB 256
#define SS 2048
#define EE 64
#define HH 128
#define G4 512   // 4*H

// x_proj scratch: [S][B][4H] fp32 = 1.07 GB
__device__ float g_xp[(size_t)SS * BB * G4];

__device__ __forceinline__ float sigm_f(float x) {
    return 1.0f / (1.0f + __expf(-x));
}
__device__ __forceinline__ float tanh_f(float x) {
    return 2.0f / (1.0f + __expf(-2.0f * x)) - 1.0f;
}

// ---- f32x2 packed-math helpers (sm_103a) ------------------------------------
typedef unsigned long long ull;

__device__ __forceinline__ ull fma2(ull a, ull b, ull c) {
    ull d;
    asm("fma.rn.f32x2 %0, %1, %2, %3;" : "=l"(d) : "l"(a), "l"(b), "l"(c));
    return d;
}
// bf16x2 (lo half = w_k, hi half = w_{k+1}) -> f32x2 (w_k, w_{k+1})
__device__ __forceinline__ ull bf2f2(unsigned int w) {
    unsigned int lo = w << 16;
    unsigned int hi = w & 0xFFFF0000u;
    ull r;
    asm("mov.b64 %0, {%1, %2};" : "=l"(r) : "r"(lo), "r"(hi));
    return r;
}
__device__ __forceinline__ float hsum2(ull v) {
    float x, y;
    asm("mov.b64 {%0, %1}, %2;" : "=f"(x), "=f"(y) : "l"(v));
    return x + y;
}
__device__ __forceinline__ unsigned int f2bf2(float hi, float lo) {
    unsigned int r;
    asm("cvt.rn.satfinite.bf16x2.f32 %0, %1, %2;" : "=r"(r) : "f"(hi), "f"(lo));
    return r;
}
__device__ __forceinline__ ull dup2(float x) {
    ull r;
    asm("mov.b64 %0, {%1, %1};" : "=l"(r) : "f"(x));
    return r;
}

// ---------------------------------------------------------------------------
// Kernel 1: x_proj[s][b][f] = dot(inputs[b][s][:], U_all[f][:]) + b_u[f]
// ---------------------------------------------------------------------------
__global__ __launch_bounds__(256) void xproj_kernel(
    const float* __restrict__ inputs,   // [B][S][E]
    const float* __restrict__ U_all,    // [4H][E]
    const float* __restrict__ b_u)      // [4H]
{
    __shared__ float xT[64 * 68];  // [e][b]
    __shared__ float uT[64 * 68];  // [e][f]

    const int s      = blockIdx.z;
    const int b_base = blockIdx.y * 64;
    const int f_base = blockIdx.x * 64;
    const int tid    = threadIdx.x;
    const int e      = tid & 63;
    const int r0     = tid >> 6;

    #pragma unroll
    for (int i = 0; i < 16; i++) {
        int r = r0 + i * 4;
        xT[e * 68 + r] = inputs[((size_t)(b_base + r) * SS + s) * EE + e];
        uT[e * 68 + r] = U_all[(size_t)(f_base + r) * EE + e];
    }
    __syncthreads();

    const int bi = (tid >> 4) * 4;
    const int fi = (tid & 15) * 4;

    ull acc[4][2];
    #pragma unroll
    for (int i = 0; i < 4; i++) { acc[i][0] = 0ULL; acc[i][1] = 0ULL; }

    #pragma unroll 16
    for (int k = 0; k < 64; k++) {
        float4 xv = *reinterpret_cast<const float4*>(&xT[k * 68 + bi]);
        ulonglong2 uvp = *reinterpret_cast<const ulonglong2*>(&uT[k * 68 + fi]);
        float xa[4] = {xv.x, xv.y, xv.z, xv.w};
        #pragma unroll
        for (int i = 0; i < 4; i++) {
            ull xx = dup2(xa[i]);
            acc[i][0] = fma2(xx, uvp.x, acc[i][0]);
            acc[i][1] = fma2(xx, uvp.y, acc[i][1]);
        }
    }

    float4 bu = *reinterpret_cast<const float4*>(&b_u[f_base + fi]);
    #pragma unroll
    for (int i = 0; i < 4; i++) {
        size_t o = ((size_t)s * BB + (size_t)(b_base + bi + i)) * G4 + f_base + fi;
        float a0, a1, a2, a3;
        asm("mov.b64 {%0, %1}, %2;" : "=f"(a0), "=f"(a1) : "l"(acc[i][0]));
        asm("mov.b64 {%0, %1}, %2;" : "=f"(a2), "=f"(a3) : "l"(acc[i][1]));
        float4 v;
        v.x = a0 + bu.x;
        v.y = a1 + bu.y;
        v.z = a2 + bu.z;
        v.w = a3 + bu.w;
        *reinterpret_cast<float4*>(&g_xp[o]) = v;
    }
}

// ---------------------------------------------------------------------------
// Kernel 2: scan. 128 CTAs x 512 threads, 2 batch rows per CTA.
//   thread t: c = t>>2, kq = t&3. Each thread: quarter-k partials for 4 gate
//   columns of c (both rows) + W_d column c (W_d weights register-resident).
//   Reduction over kq via shfl butterfly (same warp). Lanes kq=0/1 do gating
//   for batch row m=0/1. Double-buffered h/c, ONE __syncthreads per step.
// Layouts:
//   wg2  : uint4[r=64][c=128], uint4 = 4 gates' bf16x2 at k-pair r, col c
//   h/c  : [buf=2][row=2][kq=4][36] floats (pad 4 -> conflict-free quarters)
// ---------------------------------------------------------------------------
#define SM_WG     0                      // 64*512 words = 131072 B
#define SM_H      131072                 // 576 floats   =   2304 B
#define SM_C      133376                 // 576 floats   =   2304 B
#define SM_RED    135680                 // 256 floats   =   1024 B
#define SMEM_BYTES 136704

#define QP 36   // padded quarter stride (floats)

__global__ __launch_bounds__(512, 1) void scan_kernel(
    const float* __restrict__ TI,      // [B][S]
    const float* __restrict__ W_all,   // [4H][H]
    const float* __restrict__ b_all,   // [4H]
    const float* __restrict__ W_d,     // [H][H]
    const float* __restrict__ b_d,     // [H]
    const float* __restrict__ W_out,   // [1][H]
    const float* __restrict__ b_out,   // [1]
    float* __restrict__ out)           // [B]
{
    extern __shared__ char smem[];
    unsigned int* wg2 = reinterpret_cast<unsigned int*>(smem + SM_WG);
    float* hb  = reinterpret_cast<float*>(smem + SM_H);   // [(buf*2+row)*4+kq][QP]
    float* cb  = reinterpret_cast<float*>(smem + SM_C);
    float* red = reinterpret_cast<float*>(smem + SM_RED);

    const int t  = threadIdx.x;
    const int b0 = blockIdx.x * 2;
    const int c  = t >> 2;      // 0..127
    const int kq = t & 3;       // 0..3

    // ---- one-time packing: wg2[r*512 + c*4 + g] ----
    for (int u = t; u < 64 * 512; u += 512) {
        int r = u >> 9, rem = u & 511;
        int cc = rem >> 2, gg = rem & 3;
        float2 wv = *reinterpret_cast<const float2*>(&W_all[(size_t)(gg * 128 + cc) * HH + 2 * r]);
        wg2[u] = f2bf2(wv.y, wv.x);
    }
    // W_d quarter -> 16 registers (step-invariant per thread)
    uint4 wdr[4];
    #pragma unroll
    for (int q = 0; q < 4; q++) {
        unsigned int w[4];
        #pragma unroll
        for (int u = 0; u < 4; u++) {
            int p = q * 4 + u;
            float2 wv = *reinterpret_cast<const float2*>(&W_d[(size_t)c * HH + kq * 32 + 2 * p]);
            w[u] = f2bf2(wv.y, wv.x);
        }
        wdr[q] = make_uint4(w[0], w[1], w[2], w[3]);
    }
    const unsigned int* wdw = reinterpret_cast<const unsigned int*>(wdr);

    // zero both h/c buffers (576 floats each)
    for (int u = t; u < 576; u += 512) { hb[u] = 0.0f; cb[u] = 0.0f; }

    // gating-lane constants (kq<2 -> m=kq)
    const int is_gate = (kq < 2);
    const int m = kq;
    float ba_r[4] = {0, 0, 0, 0}, bd_r = 0.0f, wout_r = 0.0f;
    if (is_gate) {
        #pragma unroll
        for (int g = 0; g < 4; g++) ba_r[g] = b_all[g * 128 + c];
        bd_r = b_d[c];
        wout_r = W_out[c];
    }
    const float bo = b_out[0];

    __syncthreads();

    const uint4* wgt4 = reinterpret_cast<const uint4*>(wg2) + kq * 16 * 128 + c;

    float out_acc = 0.0f;
    float c_reg = 0.0f;   // carried c for gating lane (c, m)

    for (int s = 0; s < SS; s++) {
        const int rb = s & 1;
        const int wb = rb ^ 1;

        // prefetch gating-lane globals (hidden under phase A)
        float xpv[4] = {0, 0, 0, 0}, ti = 0.0f;
        if (is_gate) {
            size_t xb = ((size_t)s * BB + b0 + m) * G4 + c;
            #pragma unroll
            for (int g = 0; g < 4; g++) xpv[g] = g_xp[xb + g * 128];
            ti = TI[(size_t)(b0 + m) * SS + s];
        }

        const ulonglong2* h0v = reinterpret_cast<const ulonglong2*>(hb + ((rb * 2 + 0) * 4 + kq) * QP);
        const ulonglong2* h1v = reinterpret_cast<const ulonglong2*>(hb + ((rb * 2 + 1) * 4 + kq) * QP);
        const ulonglong2* c0v = reinterpret_cast<const ulonglong2*>(cb + ((rb * 2 + 0) * 4 + kq) * QP);
        const ulonglong2* c1v = reinterpret_cast<const ulonglong2*>(cb + ((rb * 2 + 1) * 4 + kq) * QP);

        // ---- Phase A: quarter-k partial dots ----
        ull a0[4] = {0ULL, 0ULL, 0ULL, 0ULL};
        ull a1[4] = {0ULL, 0ULL, 0ULL, 0ULL};
        ull d0 = 0ULL, d1 = 0ULL;

        #pragma unroll
        for (int p2 = 0; p2 < 8; p2++) {
            uint4 wv0 = wgt4[(2 * p2) * 128];
            uint4 wv1 = wgt4[(2 * p2 + 1) * 128];
            ulonglong2 hh0 = h0v[p2];
            ulonglong2 hh1 = h1v[p2];
            const unsigned int* w0 = reinterpret_cast<const unsigned int*>(&wv0);
            const unsigned int* w1 = reinterpret_cast<const unsigned int*>(&wv1);
            #pragma unroll
            for (int g = 0; g < 4; g++) {
                ull wA = bf2f2(w0[g]);
                ull wB = bf2f2(w1[g]);
                a0[g] = fma2(hh0.x, wA, a0[g]);
                a0[g] = fma2(hh0.y, wB, a0[g]);
                a1[g] = fma2(hh1.x, wA, a1[g]);
                a1[g] = fma2(hh1.y, wB, a1[g]);
            }
            ulonglong2 cc0 = c0v[p2];
            ulonglong2 cc1 = c1v[p2];
            ull dA = bf2f2(wdw[2 * p2]);
            ull dB = bf2f2(wdw[2 * p2 + 1]);
            d0 = fma2(cc0.x, dA, d0);
            d0 = fma2(cc0.y, dB, d0);
            d1 = fma2(cc1.x, dA, d1);
            d1 = fma2(cc1.y, dB, d1);
        }

        // ---- shfl butterfly over kq (lanes xor 1, xor 2) ----
        float v[10];
        #pragma unroll
        for (int g = 0; g < 4; g++) { v[g] = hsum2(a0[g]); v[4 + g] = hsum2(a1[g]); }
        v[8] = hsum2(d0);
        v[9] = hsum2(d1);
        #pragma unroll
        for (int i = 0; i < 10; i++) v[i] += __shfl_xor_sync(0xFFFFFFFFu, v[i], 1);
        #pragma unroll
        for (int i = 0; i < 10; i++) v[i] += __shfl_xor_sync(0xFFFFFFFFu, v[i], 2);

        // ---- gating: lanes kq=0 (m=0) and kq=1 (m=1) ----
        if (is_gate) {
            float fg = sigm_f(v[m * 4 + 0] + ba_r[0] + xpv[0]);
            float ig = sigm_f(v[m * 4 + 1] + ba_r[1] + xpv[1]);
            float og = sigm_f(v[m * 4 + 2] + ba_r[2] + xpv[2]);
            float ct = sigm_f(v[m * 4 + 3] + ba_r[3] + xpv[3]);
            float cp = v[8 + m] + bd_r;

            float cs1  = tanh_f(cp);
            float cadj = (c_reg - cs1) + cs1 * ti;
            float cnew = fg * cadj + ig * ct;
            float hnew = og * tanh_f(cnew);
            c_reg = cnew;

            int widx = ((wb * 2 + m) * 4 + (c >> 5)) * QP + (c & 31);
            cb[widx] = cnew;
            hb[widx] = hnew;
            out_acc += hnew * wout_r;
        }
        __syncthreads();
    }

    // ---- out[b] = sum_s h_s @ W_out + S * b_out ----
    if (is_gate) red[m * 128 + c] = out_acc;
    __syncthreads();
    if (t == 0) {
        float s0 = 0.0f;
        for (int k = 0; k < 128; k++) s0 += red[k];
        out[b0] = s0 + (float)SS * bo;
    }
    if (t == 1) {
        float s1 = 0.0f;
        for (int k = 0; k < 128; k++) s1 += red[128 + k];
        out[b0 + 1] = s1 + (float)SS * bo;
    }
}

// ---------------------------------------------------------------------------
extern "C" void kernel_launch(void* const* d_in, const int* in_sizes, int n_in,
                              void* d_out, int out_size)
{
    const float* inputs = (const float*)d_in[0];
    const float* TI     = (const float*)d_in[1];
    const float* W_all  = (const float*)d_in[2];
    const float* b_all  = (const float*)d_in[3];
    const float* U_all  = (const float*)d_in[4];
    const float* b_u    = (const float*)d_in[5];
    const float* W_d    = (const float*)d_in[6];
    const float* b_d    = (const float*)d_in[7];
    const float* W_out  = (const float*)d_in[8];
    const float* b_out  = (const float*)d_in[9];
    float* out = (float*)d_out;

    xproj_kernel<<<dim3(8, 4, SS), 256>>>(inputs, U_all, b_u);

    cudaFuncSetAttribute(scan_kernel,
                         cudaFuncAttributeMaxDynamicSharedMemorySize, SMEM_BYTES);
    scan_kernel<<<128, 512, SMEM_BYTES>>>(TI, W_all, b_all, W_d, b_d,
                                          W_out, b_out, out);
}

// round 6
// speedup vs baseline: 1.5088x; 1.5088x over previous
#include <cuda_runtime.h>
#include <cuda_fp16.h>

#define BB 256
#define SS 2048
#define EE 64
#define HH 128
#define G4 512   // 4*H

// x_proj scratch: [S][B][4H] fp32 = 1.07 GB
__device__ float g_xp[(size_t)SS * BB * G4];

__device__ __forceinline__ float sigm_f(float x) {
    return 1.0f / (1.0f + __expf(-x));
}
__device__ __forceinline__ float tanh_f(float x) {
    return 2.0f / (1.0f + __expf(-2.0f * x)) - 1.0f;
}

// ---- f32x2 packed-math helpers (sm_103a) ------------------------------------
typedef unsigned long long ull;

__device__ __forceinline__ ull fma2(ull a, ull b, ull c) {
    ull d;
    asm("fma.rn.f32x2 %0, %1, %2, %3;" : "=l"(d) : "l"(a), "l"(b), "l"(c));
    return d;
}
// bf16x2 (lo half = w_k, hi half = w_{k+1}) -> f32x2 (w_k, w_{k+1})
__device__ __forceinline__ ull bf2f2(unsigned int w) {
    unsigned int lo = w << 16;
    unsigned int hi = w & 0xFFFF0000u;
    ull r;
    asm("mov.b64 %0, {%1, %2};" : "=l"(r) : "r"(lo), "r"(hi));
    return r;
}
__device__ __forceinline__ float hsum2(ull v) {
    float x, y;
    asm("mov.b64 {%0, %1}, %2;" : "=f"(x), "=f"(y) : "l"(v));
    return x + y;
}
__device__ __forceinline__ unsigned int f2bf2(float hi, float lo) {
    unsigned int r;
    asm("cvt.rn.satfinite.bf16x2.f32 %0, %1, %2;" : "=r"(r) : "f"(hi), "f"(lo));
    return r;
}
__device__ __forceinline__ ull dup2(float x) {
    ull r;
    asm("mov.b64 %0, {%1, %1};" : "=l"(r) : "f"(x));
    return r;
}

// ---------------------------------------------------------------------------
// Kernel 1: x_proj[s][b][f] = dot(inputs[b][s][:], U_all[f][:]) + b_u[f]
// ---------------------------------------------------------------------------
__global__ __launch_bounds__(256) void xproj_kernel(
    const float* __restrict__ inputs,   // [B][S][E]
    const float* __restrict__ U_all,    // [4H][E]
    const float* __restrict__ b_u)      // [4H]
{
    __shared__ float xT[64 * 68];  // [e][b]
    __shared__ float uT[64 * 68];  // [e][f]

    const int s      = blockIdx.z;
    const int b_base = blockIdx.y * 64;
    const int f_base = blockIdx.x * 64;
    const int tid    = threadIdx.x;
    const int e      = tid & 63;
    const int r0     = tid >> 6;

    #pragma unroll
    for (int i = 0; i < 16; i++) {
        int r = r0 + i * 4;
        xT[e * 68 + r] = inputs[((size_t)(b_base + r) * SS + s) * EE + e];
        uT[e * 68 + r] = U_all[(size_t)(f_base + r) * EE + e];
    }
    __syncthreads();

    const int bi = (tid >> 4) * 4;
    const int fi = (tid & 15) * 4;

    ull acc[4][2];
    #pragma unroll
    for (int i = 0; i < 4; i++) { acc[i][0] = 0ULL; acc[i][1] = 0ULL; }

    #pragma unroll 16
    for (int k = 0; k < 64; k++) {
        float4 xv = *reinterpret_cast<const float4*>(&xT[k * 68 + bi]);
        ulonglong2 uvp = *reinterpret_cast<const ulonglong2*>(&uT[k * 68 + fi]);
        float xa[4] = {xv.x, xv.y, xv.z, xv.w};
        #pragma unroll
        for (int i = 0; i < 4; i++) {
            ull xx = dup2(xa[i]);
            acc[i][0] = fma2(xx, uvp.x, acc[i][0]);
            acc[i][1] = fma2(xx, uvp.y, acc[i][1]);
        }
    }

    float4 bu = *reinterpret_cast<const float4*>(&b_u[f_base + fi]);
    #pragma unroll
    for (int i = 0; i < 4; i++) {
        size_t o = ((size_t)s * BB + (size_t)(b_base + bi + i)) * G4 + f_base + fi;
        float a0, a1, a2, a3;
        asm("mov.b64 {%0, %1}, %2;" : "=f"(a0), "=f"(a1) : "l"(acc[i][0]));
        asm("mov.b64 {%0, %1}, %2;" : "=f"(a2), "=f"(a3) : "l"(acc[i][1]));
        float4 v;
        v.x = a0 + bu.x;
        v.y = a1 + bu.y;
        v.z = a2 + bu.z;
        v.w = a3 + bu.w;
        *reinterpret_cast<float4*>(&g_xp[o]) = v;
    }
}

// ---------------------------------------------------------------------------
// Kernel 2: scan. 128 CTAs x 512 threads, 2 batch rows per CTA.
//   thread t: c = t>>2, kq = t&3. Quarter-k partials for 4 gate columns of c
//   (both rows) + W_d column c (W_d register-resident). kq-reduction via shfl
//   butterfly. Lanes kq=0/1 do gating for m=0/1. Double-buffered h/c, ONE
//   __syncthreads per step.
// Layouts (all conflict-free):
//   wg  : uint4[r_local=16][t=512]  — OWNER-THREAD-MAJOR: lane-consecutive,
//         each uint4 = 4 gates' bf16x2 for (c = t>>2, k-pair = (t&3)*16+r_local)
//   h/c : [buf=2][row=2][kq=4][QP=36] floats (kq offsets 0/4/8/12 mod 32 banks)
// ---------------------------------------------------------------------------
#define SM_WG     0                      // 16*512 uint4 = 131072 B
#define SM_H      131072                 // 576 floats   =   2304 B
#define SM_C      133376                 // 576 floats   =   2304 B
#define SM_RED    135680                 // 256 floats   =   1024 B
#define SMEM_BYTES 136704

#define QP 36   // padded quarter stride (floats)

__global__ __launch_bounds__(512, 1) void scan_kernel(
    const float* __restrict__ TI,      // [B][S]
    const float* __restrict__ W_all,   // [4H][H]
    const float* __restrict__ b_all,   // [4H]
    const float* __restrict__ W_d,     // [H][H]
    const float* __restrict__ b_d,     // [H]
    const float* __restrict__ W_out,   // [1][H]
    const float* __restrict__ b_out,   // [1]
    float* __restrict__ out)           // [B]
{
    extern __shared__ char smem[];
    unsigned int* wg = reinterpret_cast<unsigned int*>(smem + SM_WG);
    float* hb  = reinterpret_cast<float*>(smem + SM_H);   // [(buf*2+row)*4+kq][QP]
    float* cb  = reinterpret_cast<float*>(smem + SM_C);
    float* red = reinterpret_cast<float*>(smem + SM_RED);

    const int t  = threadIdx.x;
    const int b0 = blockIdx.x * 2;
    const int c  = t >> 2;      // 0..127
    const int kq = t & 3;       // 0..3

    // ---- one-time packing: owner-thread-major gate weights ----
    // word u: g = u&3, idx = u>>2, owner tt = idx&511, r_local = idx>>9
    //         cc = tt>>2, kqq = tt&3, r = kqq*16 + r_local
    for (int u = t; u < 16 * 512 * 4; u += 512) {
        int g = u & 3;
        int idx = u >> 2;
        int tt = idx & 511;
        int r_local = idx >> 9;
        int cc = tt >> 2, kqq = tt & 3;
        int r = kqq * 16 + r_local;
        float2 wv = *reinterpret_cast<const float2*>(&W_all[(size_t)(g * 128 + cc) * HH + 2 * r]);
        wg[u] = f2bf2(wv.y, wv.x);
    }
    // W_d quarter -> 16 registers (step-invariant per thread)
    uint4 wdr[4];
    #pragma unroll
    for (int q = 0; q < 4; q++) {
        unsigned int w[4];
        #pragma unroll
        for (int u = 0; u < 4; u++) {
            int p = q * 4 + u;
            float2 wv = *reinterpret_cast<const float2*>(&W_d[(size_t)c * HH + kq * 32 + 2 * p]);
            w[u] = f2bf2(wv.y, wv.x);
        }
        wdr[q] = make_uint4(w[0], w[1], w[2], w[3]);
    }
    const unsigned int* wdw = reinterpret_cast<const unsigned int*>(wdr);

    // zero both h/c buffers (576 floats each)
    for (int u = t; u < 576; u += 512) { hb[u] = 0.0f; cb[u] = 0.0f; }

    // gating-lane constants (kq<2 -> m=kq)
    const int is_gate = (kq < 2);
    const int m = kq;
    float ba_r[4] = {0, 0, 0, 0}, bd_r = 0.0f, wout_r = 0.0f;
    if (is_gate) {
        #pragma unroll
        for (int g = 0; g < 4; g++) ba_r[g] = b_all[g * 128 + c];
        bd_r = b_d[c];
        wout_r = W_out[c];
    }
    const float bo = b_out[0];

    __syncthreads();

    const uint4* wgt4 = reinterpret_cast<const uint4*>(wg) + t;   // [r_local*512]

    float out_acc = 0.0f;
    float c_reg = 0.0f;   // carried c for gating lane (c, m)

    for (int s = 0; s < SS; s++) {
        const int rb = s & 1;
        const int wb = rb ^ 1;

        // prefetch gating-lane globals (hidden under phase A)
        float xpv[4] = {0, 0, 0, 0}, ti = 0.0f;
        if (is_gate) {
            size_t xb = ((size_t)s * BB + b0 + m) * G4 + c;
            #pragma unroll
            for (int g = 0; g < 4; g++) xpv[g] = g_xp[xb + g * 128];
            ti = TI[(size_t)(b0 + m) * SS + s];
        }

        const ulonglong2* h0v = reinterpret_cast<const ulonglong2*>(hb + ((rb * 2 + 0) * 4 + kq) * QP);
        const ulonglong2* h1v = reinterpret_cast<const ulonglong2*>(hb + ((rb * 2 + 1) * 4 + kq) * QP);
        const ulonglong2* c0v = reinterpret_cast<const ulonglong2*>(cb + ((rb * 2 + 0) * 4 + kq) * QP);
        const ulonglong2* c1v = reinterpret_cast<const ulonglong2*>(cb + ((rb * 2 + 1) * 4 + kq) * QP);

        // ---- Phase A: quarter-k partial dots ----
        ull a0[4] = {0ULL, 0ULL, 0ULL, 0ULL};
        ull a1[4] = {0ULL, 0ULL, 0ULL, 0ULL};
        ull d0 = 0ULL, d1 = 0ULL;

        #pragma unroll
        for (int p2 = 0; p2 < 8; p2++) {
            uint4 wv0 = wgt4[(2 * p2) * 512];       // k-pair r_local = 2*p2
            uint4 wv1 = wgt4[(2 * p2 + 1) * 512];   // k-pair r_local = 2*p2+1
            ulonglong2 hh0 = h0v[p2];
            ulonglong2 hh1 = h1v[p2];
            const unsigned int* w0 = reinterpret_cast<const unsigned int*>(&wv0);
            const unsigned int* w1 = reinterpret_cast<const unsigned int*>(&wv1);
            #pragma unroll
            for (int g = 0; g < 4; g++) {
                ull wA = bf2f2(w0[g]);
                ull wB = bf2f2(w1[g]);
                a0[g] = fma2(hh0.x, wA, a0[g]);
                a0[g] = fma2(hh0.y, wB, a0[g]);
                a1[g] = fma2(hh1.x, wA, a1[g]);
                a1[g] = fma2(hh1.y, wB, a1[g]);
            }
            ulonglong2 cc0 = c0v[p2];
            ulonglong2 cc1 = c1v[p2];
            ull dA = bf2f2(wdw[2 * p2]);
            ull dB = bf2f2(wdw[2 * p2 + 1]);
            d0 = fma2(cc0.x, dA, d0);
            d0 = fma2(cc0.y, dB, d0);
            d1 = fma2(cc1.x, dA, d1);
            d1 = fma2(cc1.y, dB, d1);
        }

        // ---- shfl butterfly over kq (lanes xor 1, xor 2) ----
        float v[10];
        #pragma unroll
        for (int g = 0; g < 4; g++) { v[g] = hsum2(a0[g]); v[4 + g] = hsum2(a1[g]); }
        v[8] = hsum2(d0);
        v[9] = hsum2(d1);
        #pragma unroll
        for (int i = 0; i < 10; i++) v[i] += __shfl_xor_sync(0xFFFFFFFFu, v[i], 1);
        #pragma unroll
        for (int i = 0; i < 10; i++) v[i] += __shfl_xor_sync(0xFFFFFFFFu, v[i], 2);

        // ---- gating: lanes kq=0 (m=0) and kq=1 (m=1) ----
        if (is_gate) {
            float fg = sigm_f(v[m * 4 + 0] + ba_r[0] + xpv[0]);
            float ig = sigm_f(v[m * 4 + 1] + ba_r[1] + xpv[1]);
            float og = sigm_f(v[m * 4 + 2] + ba_r[2] + xpv[2]);
            float ct = sigm_f(v[m * 4 + 3] + ba_r[3] + xpv[3]);
            float cp = v[8 + m] + bd_r;

            float cs1  = tanh_f(cp);
            float cadj = (c_reg - cs1) + cs1 * ti;
            float cnew = fg * cadj + ig * ct;
            float hnew = og * tanh_f(cnew);
            c_reg = cnew;

            int widx = ((wb * 2 + m) * 4 + (c >> 5)) * QP + (c & 31);
            cb[widx] = cnew;
            hb[widx] = hnew;
            out_acc += hnew * wout_r;
        }
        __syncthreads();
    }

    // ---- out[b] = sum_s h_s @ W_out + S * b_out ----
    if (is_gate) red[m * 128 + c] = out_acc;
    __syncthreads();
    if (t == 0) {
        float s0 = 0.0f;
        for (int k = 0; k < 128; k++) s0 += red[k];
        out[b0] = s0 + (float)SS * bo;
    }
    if (t == 1) {
        float s1 = 0.0f;
        for (int k = 0; k < 128; k++) s1 += red[128 + k];
        out[b0 + 1] = s1 + (float)SS * bo;
    }
}

// ---------------------------------------------------------------------------
extern "C" void kernel_launch(void* const* d_in, const int* in_sizes, int n_in,
                              void* d_out, int out_size)
{
    const float* inputs = (const float*)d_in[0];
    const float* TI     = (const float*)d_in[1];
    const float* W_all  = (const float*)d_in[2];
    const float* b_all  = (const float*)d_in[3];
    const float* U_all  = (const float*)d_in[4];
    const float* b_u    = (const float*)d_in[5];
    const float* W_d    = (const float*)d_in[6];
    const float* b_d    = (const float*)d_in[7];
    const float* W_out  = (const float*)d_in[8];
    const float* b_out  = (const float*)d_in[9];
    float* out = (float*)d_out;

    xproj_kernel<<<dim3(8, 4, SS), 256>>>(inputs, U_all, b_u);

    cudaFuncSetAttribute(scan_kernel,
                         cudaFuncAttributeMaxDynamicSharedMemorySize, SMEM_BYTES);
    scan_kernel<<<128, 512, SMEM_BYTES>>>(TI, W_all, b_all, W_d, b_d,
                                          W_out, b_out, out);
}